// round 1
// baseline (speedup 1.0000x reference)
#include <cuda_runtime.h>
#include <mma.h>
using namespace nvcuda;

#define DIM 2048
#define NH 32
#define HD 64
#define NB 2
#define NQ 4096
#define NKV 512

// scratch (allocation-free rule: __device__ globals)
__device__ float g_q[(size_t)NB * NH * NQ * HD];   // (b,h,n,d) normalized q
__device__ float g_k[(size_t)NB * NH * NKV * HD];  // (b,h,m,d) normalized k
__device__ float g_v[(size_t)NB * NH * NKV * HD];  // (b,h,m,d) v

__device__ __forceinline__ float tf32r(float x) { return wmma::__float_to_tf32(x); }

// ---------------------------------------------------------------------------
// Projection GEMM: C[M][2048] = A[M][2048] * W^T, tiled 128x128, tf32 wmma.
// MODE 0: q (W row = j, RMSNorm, NSEQ=4096)
// MODE 1: k (row gather h*128+2d,  RMSNorm, NSEQ=512)
// MODE 2: v (row gather h*128+2d+1, no norm, NSEQ=512)
// Output layout: dst[((b*NH + h)*NSEQ + n)*64 + d]
// ---------------------------------------------------------------------------
#define BM 128
#define BN 128
#define KC 32
#define KCP 40
#define CLD 132

template <int MODE>
__global__ __launch_bounds__(256) void proj_kernel(
    const float* __restrict__ A, const float* __restrict__ W0,
    const float* __restrict__ W1)
{
    extern __shared__ float sm[];
    float* As = sm;                 // BM*KCP
    float* Bs = sm + BM * KCP;      // BN*KCP
    constexpr int NSEQ = (MODE == 0) ? NQ : NKV;

    const int m0 = blockIdx.x * BM;
    const int n0 = blockIdx.y * BN;
    const int t = threadIdx.x;
    const int lr = t >> 3;            // 0..31
    const int lc = (t & 7) << 2;      // 0..28 (float4 col)

    // resolve weight row pointers for the 4 B-tile rows this thread loads
    const float* wrow[4];
#pragma unroll
    for (int i = 0; i < 4; i++) {
        int j = n0 + lr + i * 32;
        if (MODE == 0) {
            wrow[i] = W0 + (size_t)j * DIM;
        } else {
            int h = j >> 6, d = j & 63;
            int g = h * 128 + 2 * d + (MODE == 2 ? 1 : 0);
            wrow[i] = (g < DIM) ? (W0 + (size_t)g * DIM)
                                : (W1 + (size_t)(g - DIM) * DIM);
        }
    }

    wmma::fragment<wmma::accumulator, 16, 16, 8, float> c[2][4];
#pragma unroll
    for (int i = 0; i < 2; i++)
#pragma unroll
        for (int j = 0; j < 4; j++) wmma::fill_fragment(c[i][j], 0.0f);

    const int warp = t >> 5;
    const int wr = warp & 3;    // row group of 32
    const int wc = warp >> 2;   // col group of 64

    for (int k0 = 0; k0 < DIM; k0 += KC) {
#pragma unroll
        for (int i = 0; i < 4; i++) {
            float4 v = *(const float4*)&A[(size_t)(m0 + lr + i * 32) * DIM + k0 + lc];
            float* p = &As[(lr + i * 32) * KCP + lc];
            p[0] = tf32r(v.x); p[1] = tf32r(v.y); p[2] = tf32r(v.z); p[3] = tf32r(v.w);
        }
#pragma unroll
        for (int i = 0; i < 4; i++) {
            float4 v = *(const float4*)&wrow[i][k0 + lc];
            float* p = &Bs[(lr + i * 32) * KCP + lc];
            p[0] = tf32r(v.x); p[1] = tf32r(v.y); p[2] = tf32r(v.z); p[3] = tf32r(v.w);
        }
        __syncthreads();
#pragma unroll
        for (int ks = 0; ks < KC; ks += 8) {
            wmma::fragment<wmma::matrix_a, 16, 16, 8, wmma::precision::tf32, wmma::row_major> a0, a1;
            wmma::load_matrix_sync(a0, &As[(wr * 32) * KCP + ks], KCP);
            wmma::load_matrix_sync(a1, &As[(wr * 32 + 16) * KCP + ks], KCP);
#pragma unroll
            for (int nt = 0; nt < 4; nt++) {
                wmma::fragment<wmma::matrix_b, 16, 16, 8, wmma::precision::tf32, wmma::col_major> b;
                wmma::load_matrix_sync(b, &Bs[(wc * 64 + nt * 16) * KCP + ks], KCP);
                wmma::mma_sync(c[0][nt], a0, b, c[0][nt]);
                wmma::mma_sync(c[1][nt], a1, b, c[1][nt]);
            }
        }
        __syncthreads();
    }

    // epilogue: stage to shared, per-head RMSNorm, write (b,h,seq,d)
    float* Cs = sm;  // BM*CLD floats (overlays As/Bs)
#pragma unroll
    for (int i = 0; i < 2; i++)
#pragma unroll
        for (int nt = 0; nt < 4; nt++)
            wmma::store_matrix_sync(&Cs[(wr * 32 + i * 16) * CLD + wc * 64 + nt * 16],
                                    c[i][nt], CLD, wmma::mem_row_major);
    __syncthreads();

    __shared__ float sscale[BM * 2];
    {
        int row = t >> 1, g = t & 1;
        float s = 1.0f;
        if (MODE != 2) {
            const float* cr = &Cs[row * CLD + g * 64];
            float ss = 0.0f;
#pragma unroll
            for (int d = 0; d < 64; d++) { float v = cr[d]; ss += v * v; }
            s = rsqrtf(ss * (1.0f / 64.0f) + 1e-6f);
        }
        sscale[row * 2 + g] = s;
    }
    __syncthreads();

    float* dst = (MODE == 0) ? g_q : (MODE == 1) ? g_k : g_v;
#pragma unroll
    for (int it = 0; it < 16; it++) {
        int f = t + it * 256;        // 0..4095 float4 slots
        int row = f >> 5;
        int c4 = f & 31;
        int j = c4 << 2;             // col in tile
        int g = j >> 6;
        int d = j & 63;
        int gi = m0 + row;
        int bb = gi / NSEQ, n = gi % NSEQ;
        int h = (n0 >> 6) + g;
        float sc = sscale[row * 2 + g];
        const float* cr = &Cs[row * CLD + j];
        float4 v;
        v.x = cr[0] * sc; v.y = cr[1] * sc; v.z = cr[2] * sc; v.w = cr[3] * sc;
        *(float4*)&dst[(((size_t)bb * NH + h) * NSEQ + n) * HD + d] = v;
    }
}

// ---------------------------------------------------------------------------
// Fused attention: per (b, h, 32-query tile). Full 32x512 score row in smem,
// single-pass softmax, P*V accumulated in wmma fragments over 8 V tiles.
// ---------------------------------------------------------------------------
#define TQ 32
#define QLD 72
#define SLD 520
// smem float offsets
#define OFF_Q   0
#define OFF_KV  2304
#define OFF_S   6912
#define OFF_PM  23552
#define OFF_RS  23680
#define ATTN_FLOATS 23712

__global__ __launch_bounds__(128) void attn_kernel(float* __restrict__ out)
{
    extern __shared__ float sm[];
    float* Qs = sm + OFF_Q;     // TQ x QLD
    float* KVs = sm + OFF_KV;   // 64 x QLD
    float* Ss = sm + OFF_S;     // TQ x SLD
    float* pm = sm + OFF_PM;    // 128 partials
    float* rstat = sm + OFF_RS; // 32 row stats

    const int t = threadIdx.x;
    const int q0 = blockIdx.x * TQ;
    const int h = blockIdx.y;
    const int b = blockIdx.z;

    const float* qbase = g_q + (((size_t)b * NH + h) * NQ + q0) * HD;
    const float* kbase = g_k + ((size_t)b * NH + h) * NKV * HD;
    const float* vbase = g_v + ((size_t)b * NH + h) * NKV * HD;

    // load Q tile, fold in softmax scale 1/8
#pragma unroll
    for (int it = 0; it < 4; it++) {
        int f = t + it * 128;
        int r = f >> 4, c4 = (f & 15) << 2;
        float4 v = *(const float4*)&qbase[r * HD + c4];
        float* p = &Qs[r * QLD + c4];
        p[0] = tf32r(v.x * 0.125f); p[1] = tf32r(v.y * 0.125f);
        p[2] = tf32r(v.z * 0.125f); p[3] = tf32r(v.w * 0.125f);
    }

    const int warp = t >> 5;
    const int rowt = warp & 1;          // 16-row tile of the 32 queries
    const int ct0 = (warp >> 1) * 2;    // two 16-col tiles per warp

    // S = (Q/8) K^T  -> Ss
    for (int kt = 0; kt < 8; kt++) {
        __syncthreads();
#pragma unroll
        for (int it = 0; it < 8; it++) {
            int f = t + it * 128;
            int r = f >> 4, c4 = (f & 15) << 2;
            float4 v = *(const float4*)&kbase[(kt * 64 + r) * HD + c4];
            float* p = &KVs[r * QLD + c4];
            p[0] = tf32r(v.x); p[1] = tf32r(v.y); p[2] = tf32r(v.z); p[3] = tf32r(v.w);
        }
        __syncthreads();
#pragma unroll
        for (int ctt = 0; ctt < 2; ctt++) {
            int ct = ct0 + ctt;
            wmma::fragment<wmma::accumulator, 16, 16, 8, float> s;
            wmma::fill_fragment(s, 0.0f);
#pragma unroll
            for (int ks = 0; ks < 8; ks++) {
                wmma::fragment<wmma::matrix_a, 16, 16, 8, wmma::precision::tf32, wmma::row_major> a;
                wmma::load_matrix_sync(a, &Qs[rowt * 16 * QLD + ks * 8], QLD);
                wmma::fragment<wmma::matrix_b, 16, 16, 8, wmma::precision::tf32, wmma::col_major> bb;
                wmma::load_matrix_sync(bb, &KVs[ct * 16 * QLD + ks * 8], QLD);
                wmma::mma_sync(s, a, bb, s);
            }
            wmma::store_matrix_sync(&Ss[rowt * 16 * SLD + kt * 64 + ct * 16], s, SLD,
                                    wmma::mem_row_major);
        }
    }
    __syncthreads();

    // softmax over 512 per row (no online rescale needed)
    {
        int row = t >> 2, seg = t & 3;
        float* base = &Ss[row * SLD + seg * 128];
        float m = -1e30f;
        for (int c = 0; c < 128; c++) m = fmaxf(m, base[c]);
        pm[t] = m;
        __syncthreads();
        if (t < TQ)
            rstat[t] = fmaxf(fmaxf(pm[t * 4], pm[t * 4 + 1]),
                             fmaxf(pm[t * 4 + 2], pm[t * 4 + 3]));
        __syncthreads();
        float mm = rstat[row];
        float ssum = 0.0f;
        for (int c = 0; c < 128; c++) {
            float e = __expf(base[c] - mm);
            base[c] = e;
            ssum += e;
        }
        pm[t] = ssum;
        __syncthreads();
        if (t < TQ)
            rstat[t] = 1.0f / (pm[t * 4] + pm[t * 4 + 1] + pm[t * 4 + 2] + pm[t * 4 + 3]);
        __syncthreads();
        float rinv = rstat[row];
        for (int c = 0; c < 128; c++) base[c] = tf32r(base[c] * rinv);
    }

    // O = P V, fragment accumulation across 8 V tiles
    wmma::fragment<wmma::accumulator, 16, 16, 8, float> o[2];
    wmma::fill_fragment(o[0], 0.0f);
    wmma::fill_fragment(o[1], 0.0f);
    for (int vt = 0; vt < 8; vt++) {
        __syncthreads();
#pragma unroll
        for (int it = 0; it < 8; it++) {
            int f = t + it * 128;
            int r = f >> 4, c4 = (f & 15) << 2;
            float4 v = *(const float4*)&vbase[(vt * 64 + r) * HD + c4];
            float* p = &KVs[r * QLD + c4];
            p[0] = tf32r(v.x); p[1] = tf32r(v.y); p[2] = tf32r(v.z); p[3] = tf32r(v.w);
        }
        __syncthreads();
#pragma unroll
        for (int ks = 0; ks < 8; ks++) {
            wmma::fragment<wmma::matrix_a, 16, 16, 8, wmma::precision::tf32, wmma::row_major> a;
            wmma::load_matrix_sync(a, &Ss[rowt * 16 * SLD + vt * 64 + ks * 8], SLD);
#pragma unroll
            for (int ctt = 0; ctt < 2; ctt++) {
                int ct = ct0 + ctt;
                wmma::fragment<wmma::matrix_b, 16, 16, 8, wmma::precision::tf32, wmma::row_major> bb;
                wmma::load_matrix_sync(bb, &KVs[ks * 8 * QLD + ct * 16], QLD);
                wmma::mma_sync(o[ctt], a, bb, o[ctt]);
            }
        }
    }
    __syncthreads();
    // stage O into Qs and write out (b, n, h*64+d)
    wmma::store_matrix_sync(&Qs[rowt * 16 * QLD + ct0 * 16], o[0], QLD, wmma::mem_row_major);
    wmma::store_matrix_sync(&Qs[rowt * 16 * QLD + (ct0 + 1) * 16], o[1], QLD, wmma::mem_row_major);
    __syncthreads();
#pragma unroll
    for (int it = 0; it < 4; it++) {
        int f = t + it * 128;
        int r = f >> 4, c4 = (f & 15) << 2;
        float4 v = *(const float4*)&Qs[r * QLD + c4];
        *(float4*)&out[((size_t)b * NQ + q0 + r) * DIM + h * HD + c4] = v;
    }
}

// ---------------------------------------------------------------------------
extern "C" void kernel_launch(void* const* d_in, const int* in_sizes, int n_in,
                              void* d_out, int out_size)
{
    const float* x  = (const float*)d_in[0];
    const float* cx = (const float*)d_in[1];
    const float* Wq = (const float*)d_in[2];
    const float* Wk = (const float*)d_in[3];
    const float* Wv = (const float*)d_in[4];
    float* out = (float*)d_out;

    const int PROJ_SMEM = BM * CLD * sizeof(float);      // 67584 B
    const int ATTN_SMEM = ATTN_FLOATS * sizeof(float);   // 94848 B

    cudaFuncSetAttribute((const void*)proj_kernel<0>,
                         cudaFuncAttributeMaxDynamicSharedMemorySize, PROJ_SMEM);
    cudaFuncSetAttribute((const void*)proj_kernel<1>,
                         cudaFuncAttributeMaxDynamicSharedMemorySize, PROJ_SMEM);
    cudaFuncSetAttribute((const void*)proj_kernel<2>,
                         cudaFuncAttributeMaxDynamicSharedMemorySize, PROJ_SMEM);
    cudaFuncSetAttribute((const void*)attn_kernel,
                         cudaFuncAttributeMaxDynamicSharedMemorySize, ATTN_SMEM);

    // q projection: M = 2*4096 = 8192 rows
    proj_kernel<0><<<dim3(64, 16), 256, PROJ_SMEM>>>(x, Wq, Wq);
    // k / v projections: M = 2*512 = 1024 rows, interleaved weight-row gather
    proj_kernel<1><<<dim3(8, 16), 256, PROJ_SMEM>>>(cx, Wk, Wv);
    proj_kernel<2><<<dim3(8, 16), 256, PROJ_SMEM>>>(cx, Wk, Wv);
    // fused attention
    attn_kernel<<<dim3(NQ / TQ, NH, NB), 128, ATTN_SMEM>>>(out);
}